// round 1
// baseline (speedup 1.0000x reference)
#include <cuda_runtime.h>
#include <cuda_bf16.h>
#include <math.h>

// ---------------------------------------------------------------------------
// Swin Transformer block, fp32 baseline.
// B=64, H=W=56, C=192, window 7x7 (N=49), shift 3, heads 6 x 32, hidden 768.
// ---------------------------------------------------------------------------

#define BATCH   64
#define HH      56
#define WW_     56
#define CC      192
#define WS_     7
#define SS_     3
#define NH_     6
#define HD_     32
#define NTOK    49              // tokens per window
#define NWIMG   64              // windows per image (8x8)
#define NWIN    (BATCH * NWIMG) // 4096
#define MROWS   (NWIN * NTOK)   // 200704 (== BATCH*3136)
#define HIDDEN  768
#define EPS_    1e-5f

// ------------------------------- scratch -----------------------------------
__device__ float g_ln   [(size_t)MROWS * CC];      // LN output (reused ln1/ln2)
__device__ float g_q    [(size_t)NWIN * NH_ * NTOK * HD_];
__device__ float g_k    [(size_t)NWIN * NH_ * NTOK * HD_];
__device__ float g_v    [(size_t)NWIN * NH_ * NTOK * HD_];
__device__ float g_attn [(size_t)MROWS * CC];      // attention out, (win*49+tok, head*32+d)
__device__ float g_xnew [(size_t)MROWS * CC];      // x + attn branch (natural layout)
__device__ float g_hid  [(size_t)MROWS * HIDDEN];
__device__ int   g_rowmap[MROWS];

// -------------------------- row map (shift + windows) -----------------------
// window-order row m -> natural row index (b*3136 + oh*56 + ow), where
// (oh,ow) = ((gh+3)%56, (gw+3)%56) and (gh,gw) is the shifted-image position.
__global__ void rowmap_kernel() {
    int m = blockIdx.x * 256 + threadIdx.x;
    if (m >= MROWS) return;
    int bwin = m / NTOK, tok = m - bwin * NTOK;
    int b  = bwin >> 6, w = bwin & 63;
    int wh = w >> 3, ww = w & 7;
    int r = tok / WS_, c = tok - r * WS_;
    int gh = wh * WS_ + r, gw = ww * WS_ + c;
    int oh = gh + SS_; if (oh >= HH)  oh -= HH;
    int ow = gw + SS_; if (ow >= WW_) ow -= WW_;
    g_rowmap[m] = (b * (HH * WW_) + oh * WW_ + ow);
}

// ------------------------------ LayerNorm -----------------------------------
// one warp per row of 192
__global__ void ln_kernel(const float* __restrict__ in,
                          const float* __restrict__ w,
                          const float* __restrict__ b,
                          float* __restrict__ out) {
    int row  = blockIdx.x * 8 + (threadIdx.x >> 5);
    int lane = threadIdx.x & 31;
    const float* p = in + (size_t)row * CC;
    float v[6];
    float s = 0.f;
#pragma unroll
    for (int i = 0; i < 6; i++) { v[i] = p[lane + 32 * i]; s += v[i]; }
#pragma unroll
    for (int o = 16; o > 0; o >>= 1) s += __shfl_xor_sync(0xffffffffu, s, o);
    float mean = s * (1.f / CC);
    float q = 0.f;
#pragma unroll
    for (int i = 0; i < 6; i++) { float d = v[i] - mean; q += d * d; }
#pragma unroll
    for (int o = 16; o > 0; o >>= 1) q += __shfl_xor_sync(0xffffffffu, q, o);
    float inv = rsqrtf(q * (1.f / CC) + EPS_);
    float* op = out + (size_t)row * CC;
#pragma unroll
    for (int i = 0; i < 6; i++) {
        int c = lane + 32 * i;
        op[c] = (v[i] - mean) * inv * w[c] + b[c];
    }
}

// -------------------------------- GEMM --------------------------------------
// C[M,Ncols] = A[M,K] * B[K,Ncols] (+bias) with fused epilogues.
// BM=128, BN=64, BK=8, 256 threads, 8x4 per thread.
// MODE 0: QKV  (gather A rows via rowmap, scatter to q/k/v head layout)
// MODE 1: PROJ (out scatter via rowmap into g_xnew, + shortcut x)
// MODE 2: FC1  (exact GELU -> g_hid)
// MODE 3: FC2  (+ g_xnew residual -> dout)
template<int K, int MODE>
__global__ __launch_bounds__(256)
void gemm_kernel(const float* __restrict__ A,
                 const float* __restrict__ Bw,
                 const float* __restrict__ bias,
                 int Ncols,
                 const float* __restrict__ aux,   // x (MODE1) / unused
                 float* __restrict__ outp)        // dout (MODE3) / unused
{
    __shared__ __align__(16) float As[8][128];
    __shared__ __align__(16) float Bs[8][64];

    const int tid = threadIdx.x;
    const int tx = tid & 15, ty = tid >> 4;
    const int blockM = blockIdx.x * 128;
    const int blockN = blockIdx.y * 64;

    // A load: row = tid>>1 (0..127), 4-col group = (tid&1)*4
    int arow = blockM + (tid >> 1);
    int arow_g = (MODE == 0) ? g_rowmap[arow] : arow;
    const float* Aptr = A + (size_t)arow_g * K + (tid & 1) * 4;
    // B load: row = tid>>5 (0..7), col pair = (tid&31)*2
    const float* Bptr = Bw + (size_t)(tid >> 5) * Ncols + blockN + (tid & 31) * 2;

    float acc[8][4];
#pragma unroll
    for (int i = 0; i < 8; i++)
#pragma unroll
        for (int j = 0; j < 4; j++) acc[i][j] = 0.f;

#pragma unroll 2
    for (int k0 = 0; k0 < K; k0 += 8) {
        float4 a4 = *(const float4*)Aptr;  Aptr += 8;
        float2 b2 = *(const float2*)Bptr;  Bptr += (size_t)8 * Ncols;
        int ac = (tid & 1) * 4, am = tid >> 1;
        As[ac + 0][am] = a4.x; As[ac + 1][am] = a4.y;
        As[ac + 2][am] = a4.z; As[ac + 3][am] = a4.w;
        *(float2*)&Bs[tid >> 5][(tid & 31) * 2] = b2;
        __syncthreads();
#pragma unroll
        for (int kk = 0; kk < 8; kk++) {
            float ar[8], br[4];
            *(float4*)&ar[0] = *(const float4*)&As[kk][ty * 8];
            *(float4*)&ar[4] = *(const float4*)&As[kk][ty * 8 + 4];
            *(float4*)&br[0] = *(const float4*)&Bs[kk][tx * 4];
#pragma unroll
            for (int i = 0; i < 8; i++)
#pragma unroll
                for (int j = 0; j < 4; j++) acc[i][j] += ar[i] * br[j];
        }
        __syncthreads();
    }

    // ------------------------------ epilogue --------------------------------
#pragma unroll
    for (int i = 0; i < 8; i++) {
        int m = blockM + ty * 8 + i;
#pragma unroll
        for (int j = 0; j < 4; j++) {
            int n = blockN + tx * 4 + j;
            float val = acc[i][j] + bias[n];
            if (MODE == 0) {            // QKV scatter
                int which = n / CC;
                int rem   = n - which * CC;
                int h = rem >> 5, dd = rem & 31;
                int bwin = m / NTOK, tok = m - bwin * NTOK;
                size_t dst = ((size_t)(bwin * NH_ + h) * NTOK + tok) * HD_ + dd;
                float* dstp = (which == 0) ? g_q : (which == 1) ? g_k : g_v;
                dstp[dst] = val;
            } else if (MODE == 1) {     // proj + window reverse + shortcut
                int row = g_rowmap[m];
                size_t idx = (size_t)row * CC + n;
                g_xnew[idx] = aux[idx] + val;
            } else if (MODE == 2) {     // fc1 + exact GELU
                float g = 0.5f * val * (1.f + erff(val * 0.70710678118654752f));
                g_hid[(size_t)m * HIDDEN + n] = g;
            } else {                    // fc2 + residual
                size_t idx = (size_t)m * CC + n;
                outp[idx] = g_xnew[idx] + val;
            }
        }
    }
}

// ------------------------------ attention -----------------------------------
// one block per (window, head): 49x49 attention with rel-pos bias + shift mask
__global__ __launch_bounds__(256)
void attn_kernel(const float* __restrict__ rpb) {
    __shared__ __align__(16) float sq[NTOK * 33];
    __shared__ __align__(16) float sk[NTOK * 33];
    __shared__ __align__(16) float sv[NTOK * 33];
    __shared__ float sS[NTOK * 50];
    __shared__ float srpb[169];
    __shared__ int   slabel[NTOK];

    const int bwin = blockIdx.x;
    const int head = blockIdx.y;
    const int tid  = threadIdx.x;
    const float scale = 0.17677669529663687f;   // 1/sqrt(32)

    const size_t base = (size_t)(bwin * NH_ + head) * NTOK * HD_;
    for (int idx = tid; idx < NTOK * HD_; idx += 256) {
        int tok = idx >> 5, d = idx & 31;
        sq[tok * 33 + d] = g_q[base + idx] * scale;
        sk[tok * 33 + d] = g_k[base + idx];
        sv[tok * 33 + d] = g_v[base + idx];
    }
    for (int t = tid; t < 169; t += 256) srpb[t] = rpb[t * NH_ + head];
    if (tid < NTOK) {
        int w = bwin & 63;
        int wh = w >> 3, ww = w & 7;
        int r = tid / WS_, c = tid - r * WS_;
        int gh = wh * WS_ + r, gw = ww * WS_ + c;
        int rr = (gh < HH - WS_) ? 0 : (gh < HH - SS_) ? 1 : 2;
        int cc = (gw < WW_ - WS_) ? 0 : (gw < WW_ - SS_) ? 1 : 2;
        slabel[tid] = rr * 3 + cc;
    }
    __syncthreads();

    // S = q k^T + bias + mask
    for (int e = tid; e < NTOK * NTOK; e += 256) {
        int i = e / NTOK, j = e - i * NTOK;
        const float* qi = &sq[i * 33];
        const float* kj = &sk[j * 33];
        float a = 0.f;
#pragma unroll
        for (int d = 0; d < HD_; d++) a += qi[d] * kj[d];
        int ri = i / WS_, ci = i - ri * WS_;
        int rj = j / WS_, cj = j - rj * WS_;
        a += srpb[(ri - rj + 6) * 13 + (ci - cj + 6)];
        if (slabel[i] != slabel[j]) a -= 100.f;
        sS[i * 50 + j] = a;
    }
    __syncthreads();

    // softmax: warp per row
    {
        int warp = tid >> 5, lane = tid & 31;
        for (int i = warp; i < NTOK; i += 8) {
            float mx = -1e30f;
            for (int j = lane; j < NTOK; j += 32) mx = fmaxf(mx, sS[i * 50 + j]);
#pragma unroll
            for (int o = 16; o > 0; o >>= 1) mx = fmaxf(mx, __shfl_xor_sync(0xffffffffu, mx, o));
            float s = 0.f;
            for (int j = lane; j < NTOK; j += 32) {
                float e = __expf(sS[i * 50 + j] - mx);
                sS[i * 50 + j] = e;
                s += e;
            }
#pragma unroll
            for (int o = 16; o > 0; o >>= 1) s += __shfl_xor_sync(0xffffffffu, s, o);
            float inv = 1.f / s;
            for (int j = lane; j < NTOK; j += 32) sS[i * 50 + j] *= inv;
        }
    }
    __syncthreads();

    // O = P V  -> g_attn[(bwin*49+i)*192 + head*32 + d]
    for (int e = tid; e < NTOK * HD_; e += 256) {
        int i = e >> 5, d = e & 31;
        float a = 0.f;
        const float* Si = &sS[i * 50];
#pragma unroll
        for (int j = 0; j < NTOK; j++) a += Si[j] * sv[j * 33 + d];
        g_attn[((size_t)(bwin * NTOK + i)) * CC + head * HD_ + d] = a;
    }
}

// ------------------------------- launch -------------------------------------
extern "C" void kernel_launch(void* const* d_in, const int* in_sizes, int n_in,
                              void* d_out, int out_size) {
    const float* x       = (const float*)d_in[0];
    const float* norm1_w = (const float*)d_in[1];
    const float* norm1_b = (const float*)d_in[2];
    const float* qkv_w   = (const float*)d_in[3];
    const float* qkv_b   = (const float*)d_in[4];
    const float* rpb     = (const float*)d_in[5];
    const float* proj_w  = (const float*)d_in[6];
    const float* proj_b  = (const float*)d_in[7];
    const float* norm2_w = (const float*)d_in[8];
    const float* norm2_b = (const float*)d_in[9];
    const float* fc1_w   = (const float*)d_in[10];
    const float* fc1_b   = (const float*)d_in[11];
    const float* fc2_w   = (const float*)d_in[12];
    const float* fc2_b   = (const float*)d_in[13];
    float* out = (float*)d_out;

    float *p_ln, *p_attn, *p_hid;
    cudaGetSymbolAddress((void**)&p_ln,   g_ln);
    cudaGetSymbolAddress((void**)&p_attn, g_attn);
    cudaGetSymbolAddress((void**)&p_hid,  g_hid);

    rowmap_kernel<<<(MROWS + 255) / 256, 256>>>();

    // LN1 (natural layout)
    ln_kernel<<<MROWS / 8, 256>>>(x, norm1_w, norm1_b, p_ln);

    // QKV: (200704,192) x (192,576), A gathered through rowmap
    gemm_kernel<192, 0><<<dim3(MROWS / 128, 576 / 64), 256>>>(
        p_ln, qkv_w, qkv_b, 576, nullptr, nullptr);

    // windowed attention
    attn_kernel<<<dim3(NWIN, NH_), 256>>>(rpb);

    // proj: (200704,192) x (192,192), scatter + shortcut -> g_xnew
    gemm_kernel<192, 1><<<dim3(MROWS / 128, CC / 64), 256>>>(
        p_attn, proj_w, proj_b, CC, x, nullptr);

    // LN2
    float* p_xnew; cudaGetSymbolAddress((void**)&p_xnew, g_xnew);
    ln_kernel<<<MROWS / 8, 256>>>(p_xnew, norm2_w, norm2_b, p_ln);

    // fc1 + GELU: (200704,192) x (192,768)
    gemm_kernel<192, 2><<<dim3(MROWS / 128, HIDDEN / 64), 256>>>(
        p_ln, fc1_w, fc1_b, HIDDEN, nullptr, nullptr);

    // fc2 + residual: (200704,768) x (768,192) -> out
    gemm_kernel<768, 3><<<dim3(MROWS / 128, CC / 64), 256>>>(
        p_hid, fc2_w, fc2_b, CC, nullptr, out);
}

// round 4
// speedup vs baseline: 1.2621x; 1.2621x over previous
#include <cuda_runtime.h>
#include <cuda_bf16.h>
#include <math.h>
#include <stdint.h>

// ---------------------------------------------------------------------------
// Swin block: mma.sync bf16-split GEMMs (3xBF16) + fused epilogues + attention.
// B=64, H=W=56, C=192, ws=7 (N=49), shift=3, heads 6x32, hidden 768.
// ---------------------------------------------------------------------------

#define BATCH   64
#define HH      56
#define WW_     56
#define CC      192
#define WS_     7
#define SS_     3
#define NH_     6
#define HD_     32
#define NTOK    49
#define NWIN    4096
#define MROWS   200704
#define HIDDEN  768
#define EPS_    1e-5f

// ------------------------------- scratch -----------------------------------
__device__ float g_ln   [(size_t)MROWS * CC];
__device__ float g_qkv  [(size_t)MROWS * 576];     // window-order rows
__device__ float g_attn [(size_t)MROWS * CC];      // window-order rows
__device__ float g_xnew [(size_t)MROWS * CC];      // natural rows
__device__ float g_hid  [(size_t)MROWS * HIDDEN];
__device__ int   g_rowmap[MROWS];
// split weights: [N rows, 2K cols] bf16 (cols [0,K)=hi, [K,2K)=lo)
__device__ __nv_bfloat16 g_wqkv [576 * 2 * 192];
__device__ __nv_bfloat16 g_wproj[192 * 2 * 192];
__device__ __nv_bfloat16 g_wfc1 [768 * 2 * 192];
__device__ __nv_bfloat16 g_wfc2 [192 * 2 * 768];

// ------------------------------ helpers -------------------------------------
__device__ __forceinline__ uint32_t smem_u32(const void* p) {
    uint32_t a;
    asm("{ .reg .u64 t; cvta.to.shared.u64 t, %1; cvt.u32.u64 %0, t; }"
        : "=r"(a) : "l"(p));
    return a;
}
#define SWZ(o) ((o) ^ (((o) >> 3) & 0x70))

__device__ __forceinline__ void ldm4(uint32_t* r, uint32_t addr) {
    asm volatile("ldmatrix.sync.aligned.m8n8.x4.shared.b16 {%0,%1,%2,%3}, [%4];"
                 : "=r"(r[0]), "=r"(r[1]), "=r"(r[2]), "=r"(r[3]) : "r"(addr));
}
__device__ __forceinline__ void mma16816(float* c, const uint32_t* a,
                                         uint32_t b0, uint32_t b1) {
    asm volatile(
        "mma.sync.aligned.m16n8k16.row.col.f32.bf16.bf16.f32 "
        "{%0,%1,%2,%3}, {%4,%5,%6,%7}, {%8,%9}, {%0,%1,%2,%3};"
        : "+f"(c[0]), "+f"(c[1]), "+f"(c[2]), "+f"(c[3])
        : "r"(a[0]), "r"(a[1]), "r"(a[2]), "r"(a[3]), "r"(b0), "r"(b1));
}
__device__ __forceinline__ uint32_t b2u(__nv_bfloat162 v) { return *(uint32_t*)&v; }

// -------------------------- small prep kernels ------------------------------
__global__ void rowmap_kernel() {
    int m = blockIdx.x * 256 + threadIdx.x;
    if (m >= MROWS) return;
    int bwin = m / NTOK, tok = m - bwin * NTOK;
    int b  = bwin >> 6, w = bwin & 63;
    int wh = w >> 3, ww = w & 7;
    int r = tok / WS_, c = tok - r * WS_;
    int gh = wh * WS_ + r, gw = ww * WS_ + c;
    int oh = gh + SS_; if (oh >= HH)  oh -= HH;
    int ow = gw + SS_; if (ow >= WW_) ow -= WW_;
    g_rowmap[m] = (b * (HH * WW_) + oh * WW_ + ow);
}

__global__ void wsplit_kernel(const float* __restrict__ W,
                              __nv_bfloat16* __restrict__ out, int Kd, int Nd) {
    int idx = blockIdx.x * 256 + threadIdx.x;
    if (idx >= Kd * Nd) return;
    int k = idx / Nd, n = idx - k * Nd;
    float x = W[idx];
    __nv_bfloat16 h = __float2bfloat16(x);
    float lo = x - __bfloat162float(h);
    out[(size_t)n * (2 * Kd) + k]      = h;
    out[(size_t)n * (2 * Kd) + Kd + k] = __float2bfloat16(lo);
}

__global__ void ln_kernel(const float* __restrict__ in,
                          const float* __restrict__ w,
                          const float* __restrict__ b,
                          float* __restrict__ out) {
    int row  = blockIdx.x * 8 + (threadIdx.x >> 5);
    int lane = threadIdx.x & 31;
    const float* p = in + (size_t)row * CC;
    float v[6];
    float s = 0.f;
#pragma unroll
    for (int i = 0; i < 6; i++) { v[i] = p[lane + 32 * i]; s += v[i]; }
#pragma unroll
    for (int o = 16; o > 0; o >>= 1) s += __shfl_xor_sync(0xffffffffu, s, o);
    float mean = s * (1.f / CC);
    float q = 0.f;
#pragma unroll
    for (int i = 0; i < 6; i++) { float d = v[i] - mean; q += d * d; }
#pragma unroll
    for (int o = 16; o > 0; o >>= 1) q += __shfl_xor_sync(0xffffffffu, q, o);
    float inv = rsqrtf(q * (1.f / CC) + EPS_);
    float* op = out + (size_t)row * CC;
#pragma unroll
    for (int i = 0; i < 6; i++) {
        int c = lane + 32 * i;
        op[c] = (v[i] - mean) * inv * w[c] + b[c];
    }
}

// ----------------------------- mma GEMM --------------------------------------
// C[128,64] = A[128,K] fp32 (split hi/lo on the fly) x Bsplit[N,2K]^T bf16.
// 3 terms: hiA*hiB + loA*hiB + hiA*loB.  BK=32 fp32-k per chunk.
// SMEM rows: [32 hi bf16 | 32 lo bf16] = 128B, xor-swizzled.
// MODE 0: QKV (A rows gathered via rowmap -> g_qkv[m,576])
// MODE 1: proj (scatter via rowmap + shortcut -> g_xnew)
// MODE 2: fc1 + exact GELU -> g_hid
// MODE 3: fc2 + residual -> outp
template<int K, int MODE>
__global__ __launch_bounds__(256, 2)
void mma_gemm(const float* __restrict__ A,
              const __nv_bfloat16* __restrict__ Bsp,
              const float* __restrict__ bias,
              const float* __restrict__ aux,
              float* __restrict__ outp)
{
    __shared__ __align__(128) char smA[2][16384];   // 128 rows x 128B
    __shared__ __align__(128) char smB[2][8192];    // 64 rows x 128B
    constexpr int NCH = K / 32;

    const int tid  = threadIdx.x;
    const int lane = tid & 31;
    const int warp = tid >> 5;
    const int wm = warp & 3;        // M quarter (32 rows)
    const int wn = warp >> 2;       // N half (32 cols)
    const int blockN = blockIdx.x * 64;
    const int blockM = blockIdx.y * 128;

    // ---- per-thread load descriptors ----
    // A: 4 x (row = idx>>3, k4 = idx&7), idx = i*256 + tid
    const float* aptr[4];
    uint32_t dhi[4], dlo[4];
#pragma unroll
    for (int i = 0; i < 4; i++) {
        int idx = i * 256 + tid;
        int row = idx >> 3, k4 = idx & 7;
        int garow = (MODE == 0) ? g_rowmap[blockM + row] : (blockM + row);
        aptr[i] = A + (size_t)garow * K + k4 * 4;
        dhi[i] = SWZ((uint32_t)(row * 128 + k4 * 8));
        dlo[i] = SWZ((uint32_t)(row * 128 + 64 + k4 * 8));
    }
    // B: 2 x (n = idx>>3, half = (idx>>2)&1, c16 = idx&3)
    const __nv_bfloat16* bptr[2];
    uint32_t dB[2];
#pragma unroll
    for (int i = 0; i < 2; i++) {
        int idx = i * 256 + tid;
        int n = idx >> 3, half = (idx >> 2) & 1, c16 = idx & 3;
        bptr[i] = Bsp + (size_t)(blockN + n) * (2 * K) + half * K + c16 * 8;
        dB[i] = SWZ((uint32_t)(n * 128 + half * 64 + c16 * 16));
    }

    // ---- fragment base offsets ----
    uint32_t oA[2], oB[2];
#pragma unroll
    for (int tm = 0; tm < 2; tm++)
        oA[tm] = (uint32_t)((wm * 32 + tm * 16 + (lane & 15)) * 128 + (lane >> 4) * 16);
#pragma unroll
    for (int g = 0; g < 2; g++)
        oB[g] = (uint32_t)((wn * 32 + g * 16 + (lane & 7) + ((lane >> 4) & 1) * 8) * 128
                           + ((lane >> 3) & 1) * 16);

    float Cr[2][4][4];
#pragma unroll
    for (int a = 0; a < 2; a++)
#pragma unroll
        for (int b = 0; b < 4; b++)
#pragma unroll
            for (int c = 0; c < 4; c++) Cr[a][b][c] = 0.f;

    auto ldst = [&](int c, int st) {
#pragma unroll
        for (int i = 0; i < 4; i++) {
            float4 a4 = *(const float4*)(aptr[i] + c * 32);
            __nv_bfloat162 h01 = __floats2bfloat162_rn(a4.x, a4.y);
            __nv_bfloat162 h23 = __floats2bfloat162_rn(a4.z, a4.w);
            float l0 = a4.x - __bfloat162float(h01.x);
            float l1 = a4.y - __bfloat162float(h01.y);
            float l2 = a4.z - __bfloat162float(h23.x);
            float l3 = a4.w - __bfloat162float(h23.y);
            uint2 hv = make_uint2(b2u(h01), b2u(h23));
            uint2 lv = make_uint2(b2u(__floats2bfloat162_rn(l0, l1)),
                                  b2u(__floats2bfloat162_rn(l2, l3)));
            *(uint2*)(smA[st] + dhi[i]) = hv;
            *(uint2*)(smA[st] + dlo[i]) = lv;
        }
#pragma unroll
        for (int i = 0; i < 2; i++) {
            uint4 v = *(const uint4*)(bptr[i] + c * 32);
            *(uint4*)(smB[st] + dB[i]) = v;
        }
    };

    ldst(0, 0);
    __syncthreads();

    for (int c = 0; c < NCH; c++) {
        const int st = c & 1;
        if (c + 1 < NCH) ldst(c + 1, st ^ 1);

        const uint32_t aB = smem_u32(smA[st]);
        const uint32_t bB = smem_u32(smB[st]);
#pragma unroll
        for (int k16 = 0; k16 < 2; k16++) {
            uint32_t Ah[2][4], Al[2][4], Bh[2][4], Bl[2][4];
            const uint32_t ko = k16 * 32;
#pragma unroll
            for (int tm = 0; tm < 2; tm++) {
                ldm4(Ah[tm], aB + SWZ(oA[tm] + ko));
                ldm4(Al[tm], aB + SWZ(oA[tm] + 64 + ko));
            }
#pragma unroll
            for (int g = 0; g < 2; g++) {
                ldm4(Bh[g], bB + SWZ(oB[g] + ko));
                ldm4(Bl[g], bB + SWZ(oB[g] + 64 + ko));
            }
#pragma unroll
            for (int tm = 0; tm < 2; tm++)
#pragma unroll
                for (int tn = 0; tn < 4; tn++)
                    mma16816(Cr[tm][tn], Ah[tm],
                             Bh[tn >> 1][(tn & 1) * 2], Bh[tn >> 1][(tn & 1) * 2 + 1]);
#pragma unroll
            for (int tm = 0; tm < 2; tm++)
#pragma unroll
                for (int tn = 0; tn < 4; tn++)
                    mma16816(Cr[tm][tn], Al[tm],
                             Bh[tn >> 1][(tn & 1) * 2], Bh[tn >> 1][(tn & 1) * 2 + 1]);
#pragma unroll
            for (int tm = 0; tm < 2; tm++)
#pragma unroll
                for (int tn = 0; tn < 4; tn++)
                    mma16816(Cr[tm][tn], Ah[tm],
                             Bl[tn >> 1][(tn & 1) * 2], Bl[tn >> 1][(tn & 1) * 2 + 1]);
        }
        __syncthreads();
    }

    // ------------------------------ epilogue --------------------------------
    const int r0 = blockM + wm * 32 + (lane >> 2);
    const int n0 = blockN + wn * 32 + 2 * (lane & 3);
#pragma unroll
    for (int tm = 0; tm < 2; tm++) {
#pragma unroll
        for (int tn = 0; tn < 4; tn++) {
            int n = n0 + tn * 8;
            float bx = bias[n], by = bias[n + 1];
#pragma unroll
            for (int half = 0; half < 2; half++) {
                int m = r0 + tm * 16 + half * 8;
                float vx = Cr[tm][tn][half * 2 + 0] + bx;
                float vy = Cr[tm][tn][half * 2 + 1] + by;
                if (MODE == 0) {
                    *(float2*)(g_qkv + (size_t)m * 576 + n) = make_float2(vx, vy);
                } else if (MODE == 1) {
                    size_t idx = (size_t)g_rowmap[m] * CC + n;
                    float2 a = *(const float2*)(aux + idx);
                    *(float2*)(g_xnew + idx) = make_float2(vx + a.x, vy + a.y);
                } else if (MODE == 2) {
                    vx = 0.5f * vx * (1.f + erff(vx * 0.70710678118654752f));
                    vy = 0.5f * vy * (1.f + erff(vy * 0.70710678118654752f));
                    *(float2*)(g_hid + (size_t)m * HIDDEN + n) = make_float2(vx, vy);
                } else {
                    size_t idx = (size_t)m * CC + n;
                    float2 a = *(const float2*)(g_xnew + idx);
                    *(float2*)(outp + idx) = make_float2(vx + a.x, vy + a.y);
                }
            }
        }
    }
}

// ------------------------------ attention -----------------------------------
__global__ __launch_bounds__(256)
void attn_kernel(const float* __restrict__ rpb) {
    __shared__ __align__(16) float sq[52 * 33];
    __shared__ __align__(16) float sk[52 * 33];
    __shared__ __align__(16) float sv[52 * 33];
    __shared__ float sS[NTOK * 50];
    __shared__ float srpb[169];
    __shared__ int   slabel[NTOK];

    const int bwin = blockIdx.x;
    const int head = blockIdx.y;
    const int tid  = threadIdx.x;
    const float scale = 0.17677669529663687f;

    const size_t rbase = (size_t)(bwin * NTOK) * 576 + head * HD_;
    for (int idx = tid; idx < NTOK * HD_; idx += 256) {
        int tok = idx >> 5, d = idx & 31;
        const float* r = g_qkv + rbase + (size_t)tok * 576;
        sq[tok * 33 + d] = r[d] * scale;
        sk[tok * 33 + d] = r[192 + d];
        sv[tok * 33 + d] = r[384 + d];
    }
    for (int t = tid; t < 169; t += 256) srpb[t] = rpb[t * NH_ + head];
    if (tid < NTOK) {
        int w = bwin & 63;
        int wh = w >> 3, ww = w & 7;
        int r = tid / WS_, c = tid - r * WS_;
        int gh = wh * WS_ + r, gw = ww * WS_ + c;
        int rr = (gh < HH - WS_) ? 0 : (gh < HH - SS_) ? 1 : 2;
        int cc = (gw < WW_ - WS_) ? 0 : (gw < WW_ - SS_) ? 1 : 2;
        slabel[tid] = rr * 3 + cc;
    }
    __syncthreads();

    for (int e = tid; e < NTOK * 13; e += 256) {
        int i = e / 13, j0 = (e - i * 13) * 4;
        const float* qi = &sq[i * 33];
        const float* k0 = &sk[j0 * 33];
        float a0 = 0.f, a1 = 0.f, a2 = 0.f, a3 = 0.f;
#pragma unroll
        for (int d = 0; d < HD_; d++) {
            float qv = qi[d];
            a0 += qv * k0[d];
            a1 += qv * k0[33 + d];
            a2 += qv * k0[66 + d];
            a3 += qv * k0[99 + d];
        }
        float acc[4] = {a0, a1, a2, a3};
        int ri = i / WS_, ci = i - ri * WS_;
        int li = slabel[i];
#pragma unroll
        for (int t = 0; t < 4; t++) {
            int j = j0 + t;
            if (j < NTOK) {
                int rj = j / WS_, cj = j - rj * WS_;
                float a = acc[t] + srpb[(ri - rj + 6) * 13 + (ci - cj + 6)];
                if (li != slabel[j]) a -= 100.f;
                sS[i * 50 + j] = a;
            }
        }
    }
    __syncthreads();

    {
        int warp = tid >> 5, lane = tid & 31;
        for (int i = warp; i < NTOK; i += 8) {
            float mx = -1e30f;
            for (int j = lane; j < NTOK; j += 32) mx = fmaxf(mx, sS[i * 50 + j]);
#pragma unroll
            for (int o = 16; o > 0; o >>= 1) mx = fmaxf(mx, __shfl_xor_sync(0xffffffffu, mx, o));
            float s = 0.f;
            for (int j = lane; j < NTOK; j += 32) {
                float e = __expf(sS[i * 50 + j] - mx);
                sS[i * 50 + j] = e;
                s += e;
            }
#pragma unroll
            for (int o = 16; o > 0; o >>= 1) s += __shfl_xor_sync(0xffffffffu, s, o);
            float inv = 1.f / s;
            for (int j = lane; j < NTOK; j += 32) sS[i * 50 + j] *= inv;
        }
    }
    __syncthreads();

    for (int e = tid; e < NTOK * 8; e += 256) {
        int i = e >> 3, d0 = (e & 7) * 4;
        float a0 = 0.f, a1 = 0.f, a2 = 0.f, a3 = 0.f;
        const float* Si = &sS[i * 50];
#pragma unroll
        for (int j = 0; j < NTOK; j++) {
            float s_ = Si[j];
            const float* vj = &sv[j * 33 + d0];
            a0 += s_ * vj[0]; a1 += s_ * vj[1];
            a2 += s_ * vj[2]; a3 += s_ * vj[3];
        }
        *(float4*)(g_attn + ((size_t)(bwin * NTOK + i)) * CC + head * HD_ + d0) =
            make_float4(a0, a1, a2, a3);
    }
}

// ------------------------------- launch -------------------------------------
extern "C" void kernel_launch(void* const* d_in, const int* in_sizes, int n_in,
                              void* d_out, int out_size) {
    const float* x       = (const float*)d_in[0];
    const float* norm1_w = (const float*)d_in[1];
    const float* norm1_b = (const float*)d_in[2];
    const float* qkv_w   = (const float*)d_in[3];
    const float* qkv_b   = (const float*)d_in[4];
    const float* rpb     = (const float*)d_in[5];
    const float* proj_w  = (const float*)d_in[6];
    const float* proj_b  = (const float*)d_in[7];
    const float* norm2_w = (const float*)d_in[8];
    const float* norm2_b = (const float*)d_in[9];
    const float* fc1_w   = (const float*)d_in[10];
    const float* fc1_b   = (const float*)d_in[11];
    const float* fc2_w   = (const float*)d_in[12];
    const float* fc2_b   = (const float*)d_in[13];
    float* out = (float*)d_out;

    float *p_ln, *p_attn, *p_xnew, *p_hid;
    __nv_bfloat16 *p_wqkv, *p_wproj, *p_wfc1, *p_wfc2;
    cudaGetSymbolAddress((void**)&p_ln,    g_ln);
    cudaGetSymbolAddress((void**)&p_attn,  g_attn);
    cudaGetSymbolAddress((void**)&p_xnew,  g_xnew);
    cudaGetSymbolAddress((void**)&p_hid,   g_hid);
    cudaGetSymbolAddress((void**)&p_wqkv,  g_wqkv);
    cudaGetSymbolAddress((void**)&p_wproj, g_wproj);
    cudaGetSymbolAddress((void**)&p_wfc1,  g_wfc1);
    cudaGetSymbolAddress((void**)&p_wfc2,  g_wfc2);

    rowmap_kernel<<<(MROWS + 255) / 256, 256>>>();
    wsplit_kernel<<<(192 * 576 + 255) / 256, 256>>>(qkv_w,  p_wqkv, 192, 576);
    wsplit_kernel<<<(192 * 192 + 255) / 256, 256>>>(proj_w, p_wproj, 192, 192);
    wsplit_kernel<<<(192 * 768 + 255) / 256, 256>>>(fc1_w,  p_wfc1, 192, 768);
    wsplit_kernel<<<(768 * 192 + 255) / 256, 256>>>(fc2_w,  p_wfc2, 768, 192);

    ln_kernel<<<MROWS / 8, 256>>>(x, norm1_w, norm1_b, p_ln);

    mma_gemm<192, 0><<<dim3(9, 1568), 256>>>(p_ln, p_wqkv, qkv_b, nullptr, nullptr);

    attn_kernel<<<dim3(NWIN, NH_), 256>>>(rpb);

    mma_gemm<192, 1><<<dim3(3, 1568), 256>>>(p_attn, p_wproj, proj_b, x, nullptr);

    ln_kernel<<<MROWS / 8, 256>>>(p_xnew, norm2_w, norm2_b, p_ln);

    mma_gemm<192, 2><<<dim3(12, 1568), 256>>>(p_ln, p_wfc1, fc1_b, nullptr, nullptr);

    mma_gemm<768, 3><<<dim3(3, 1568), 256>>>(p_hid, p_wfc2, fc2_b, nullptr, out);
}

// round 5
// speedup vs baseline: 1.3172x; 1.0437x over previous
#include <cuda_runtime.h>
#include <cuda_bf16.h>
#include <math.h>
#include <stdint.h>

// ---------------------------------------------------------------------------
// Swin block: split-bf16 HMMA GEMMs with cp.async pipelines, presplit
// activations, fused epilogues, float4-vectorized windowed attention.
// ---------------------------------------------------------------------------

#define BATCH   64
#define HH      56
#define WW_     56
#define CC      192
#define WS_     7
#define SS_     3
#define NH_     6
#define HD_     32
#define NTOK    49
#define NWIN    4096
#define MROWS   200704
#define HIDDEN  768
#define EPS_    1e-5f

// ------------------------------- scratch -----------------------------------
// split-bf16 activation rows: [hi(K) | lo(K)]
__device__ __nv_bfloat16 g_ln  [(size_t)MROWS * 384];    // LN out (K=192)
__device__ __nv_bfloat16 g_attn[(size_t)MROWS * 384];    // attn out (K=192)
__device__ __nv_bfloat16 g_hid [(size_t)MROWS * 1536];   // GELU out (K=768)
__device__ float g_qkv [(size_t)MROWS * 576];            // window-order fp32
__device__ float g_xnew[(size_t)MROWS * CC];             // natural fp32
__device__ int   g_rowmap[MROWS];
// split weights: [N][2K] bf16
__device__ __nv_bfloat16 g_wqkv [576 * 2 * 192];
__device__ __nv_bfloat16 g_wproj[192 * 2 * 192];
__device__ __nv_bfloat16 g_wfc1 [768 * 2 * 192];
__device__ __nv_bfloat16 g_wfc2 [192 * 2 * 768];

// ------------------------------ helpers -------------------------------------
__device__ __forceinline__ uint32_t smem_u32(const void* p) {
    uint32_t a;
    asm("{ .reg .u64 t; cvta.to.shared.u64 t, %1; cvt.u32.u64 %0, t; }"
        : "=r"(a) : "l"(p));
    return a;
}
#define SWZ(o) ((o) ^ (((o) >> 3) & 0x70))

__device__ __forceinline__ void cp16(uint32_t dst, const void* src) {
    asm volatile("cp.async.cg.shared.global [%0], [%1], 16;"
                 :: "r"(dst), "l"(src));
}
__device__ __forceinline__ void cp_commit() {
    asm volatile("cp.async.commit_group;" ::: "memory");
}
__device__ __forceinline__ void cp_wait0() {
    asm volatile("cp.async.wait_group 0;" ::: "memory");
}
__device__ __forceinline__ void ldm4(uint32_t* r, uint32_t addr) {
    asm volatile("ldmatrix.sync.aligned.m8n8.x4.shared.b16 {%0,%1,%2,%3}, [%4];"
                 : "=r"(r[0]), "=r"(r[1]), "=r"(r[2]), "=r"(r[3]) : "r"(addr));
}
__device__ __forceinline__ void mma16816(float* c, const uint32_t* a,
                                         uint32_t b0, uint32_t b1) {
    asm volatile(
        "mma.sync.aligned.m16n8k16.row.col.f32.bf16.bf16.f32 "
        "{%0,%1,%2,%3}, {%4,%5,%6,%7}, {%8,%9}, {%0,%1,%2,%3};"
        : "+f"(c[0]), "+f"(c[1]), "+f"(c[2]), "+f"(c[3])
        : "r"(a[0]), "r"(a[1]), "r"(a[2]), "r"(a[3]), "r"(b0), "r"(b1));
}
__device__ __forceinline__ uint32_t b2u(__nv_bfloat162 v) { return *(uint32_t*)&v; }

// -------------------------- small prep kernels ------------------------------
__global__ void rowmap_kernel() {
    int m = blockIdx.x * 256 + threadIdx.x;
    if (m >= MROWS) return;
    int bwin = m / NTOK, tok = m - bwin * NTOK;
    int b  = bwin >> 6, w = bwin & 63;
    int wh = w >> 3, ww = w & 7;
    int r = tok / WS_, c = tok - r * WS_;
    int gh = wh * WS_ + r, gw = ww * WS_ + c;
    int oh = gh + SS_; if (oh >= HH)  oh -= HH;
    int ow = gw + SS_; if (ow >= WW_) ow -= WW_;
    g_rowmap[m] = (b * (HH * WW_) + oh * WW_ + ow);
}

__global__ void wsplit_kernel(const float* __restrict__ W,
                              __nv_bfloat16* __restrict__ out, int Kd, int Nd) {
    int idx = blockIdx.x * 256 + threadIdx.x;
    if (idx >= Kd * Nd) return;
    int k = idx / Nd, n = idx - k * Nd;
    float x = W[idx];
    __nv_bfloat16 h = __float2bfloat16(x);
    float lo = x - __bfloat162float(h);
    out[(size_t)n * (2 * Kd) + k]      = h;
    out[(size_t)n * (2 * Kd) + Kd + k] = __float2bfloat16(lo);
}

// LN: fp32 in -> split bf16 out ([hi192 | lo192] rows)
__global__ void ln_kernel(const float* __restrict__ in,
                          const float* __restrict__ w,
                          const float* __restrict__ b,
                          __nv_bfloat16* __restrict__ out) {
    int row  = blockIdx.x * 8 + (threadIdx.x >> 5);
    int lane = threadIdx.x & 31;
    const float* p = in + (size_t)row * CC;
    float v[6];
    float s = 0.f;
#pragma unroll
    for (int i = 0; i < 6; i++) { v[i] = p[lane + 32 * i]; s += v[i]; }
#pragma unroll
    for (int o = 16; o > 0; o >>= 1) s += __shfl_xor_sync(0xffffffffu, s, o);
    float mean = s * (1.f / CC);
    float q = 0.f;
#pragma unroll
    for (int i = 0; i < 6; i++) { float d = v[i] - mean; q += d * d; }
#pragma unroll
    for (int o = 16; o > 0; o >>= 1) q += __shfl_xor_sync(0xffffffffu, q, o);
    float inv = rsqrtf(q * (1.f / CC) + EPS_);
    __nv_bfloat16* op = out + (size_t)row * 384;
#pragma unroll
    for (int i = 0; i < 6; i++) {
        int c = lane + 32 * i;
        float y = (v[i] - mean) * inv * w[c] + b[c];
        __nv_bfloat16 h = __float2bfloat16(y);
        op[c]       = h;
        op[192 + c] = __float2bfloat16(y - __bfloat162float(h));
    }
}

// ----------------------------- mma GEMM --------------------------------------
// C[128,64] tile = Asp[128,2K] x Bsp[N,2K]^T, 3 terms hiA*hiB+loA*hiB+hiA*loB.
// BK = 64 fp32-k per chunk; cp.async double-buffered; 96KB dyn smem.
// stage layout: A-hi 16K | A-lo 16K | B-hi 8K | B-lo 8K  (128B swizzled rows)
#define STAGE_B 49152
template<int K, int MODE>
__global__ __launch_bounds__(256, 2)
void mma_gemm(const __nv_bfloat16* __restrict__ A,
              const __nv_bfloat16* __restrict__ Bsp,
              const float* __restrict__ bias,
              const float* __restrict__ aux,
              float* __restrict__ outp)
{
    extern __shared__ __align__(128) char dynsm[];
    constexpr int NCH = K / 64;
    constexpr int ARS = 2 * K;

    const int tid  = threadIdx.x;
    const int lane = tid & 31;
    const int warp = tid >> 5;
    const int wm = warp & 3;
    const int wn = warp >> 2;
    const int blockN = blockIdx.x * 64;
    const int blockM = blockIdx.y * 128;
    const uint32_t sb0 = smem_u32(dynsm);

    // per-thread cp.async descriptors
    const __nv_bfloat16* aSrc[4];
    uint32_t aDst[4];
#pragma unroll
    for (int i = 0; i < 4; i++) {
        int idx = i * 256 + tid;
        int row = idx >> 3, u = idx & 7;
        int garow = (MODE == 0) ? g_rowmap[blockM + row] : (blockM + row);
        aSrc[i] = A + (size_t)garow * ARS + u * 8;
        aDst[i] = SWZ((uint32_t)(row * 128 + u * 16));
    }
    const __nv_bfloat16* bSrc[2];
    uint32_t bDst[2];
#pragma unroll
    for (int i = 0; i < 2; i++) {
        int idx = i * 256 + tid;
        int n = idx >> 3, u = idx & 7;
        bSrc[i] = Bsp + (size_t)(blockN + n) * ARS + u * 8;
        bDst[i] = SWZ((uint32_t)(n * 128 + u * 16));
    }

    auto issue = [&](int c, int st) {
        const uint32_t sb = sb0 + st * STAGE_B;
#pragma unroll
        for (int i = 0; i < 4; i++) {
            cp16(sb + aDst[i],         aSrc[i] + c * 64);       // A hi
            cp16(sb + 16384 + aDst[i], aSrc[i] + K + c * 64);   // A lo
        }
#pragma unroll
        for (int i = 0; i < 2; i++) {
            cp16(sb + 32768 + bDst[i], bSrc[i] + c * 64);       // B hi
            cp16(sb + 40960 + bDst[i], bSrc[i] + K + c * 64);   // B lo
        }
    };

    // fragment offsets
    uint32_t oA[2], oB[2];
#pragma unroll
    for (int tm = 0; tm < 2; tm++)
        oA[tm] = (uint32_t)((wm * 32 + tm * 16 + (lane & 15)) * 128 + (lane >> 4) * 16);
#pragma unroll
    for (int g = 0; g < 2; g++)
        oB[g] = (uint32_t)((wn * 32 + g * 16 + (lane & 7) + ((lane >> 4) & 1) * 8) * 128
                           + ((lane >> 3) & 1) * 16);

    float Cr[2][4][4];
#pragma unroll
    for (int a = 0; a < 2; a++)
#pragma unroll
        for (int b = 0; b < 4; b++)
#pragma unroll
            for (int c = 0; c < 4; c++) Cr[a][b][c] = 0.f;

    issue(0, 0);
    cp_commit();

    for (int c = 0; c < NCH; c++) {
        const int st = c & 1;
        cp_wait0();
        __syncthreads();
        if (c + 1 < NCH) { issue(c + 1, st ^ 1); cp_commit(); }

        const uint32_t aH = sb0 + st * STAGE_B;
        const uint32_t aL = aH + 16384;
        const uint32_t bH = aH + 32768;
        const uint32_t bL = aH + 40960;
#pragma unroll
        for (int k16 = 0; k16 < 4; k16++) {
            const uint32_t ko = k16 * 32;
            uint32_t Ah[2][4], Al[2][4], Bh[2][4], Bl[2][4];
#pragma unroll
            for (int tm = 0; tm < 2; tm++) {
                ldm4(Ah[tm], aH + SWZ(oA[tm] + ko));
                ldm4(Al[tm], aL + SWZ(oA[tm] + ko));
            }
#pragma unroll
            for (int g = 0; g < 2; g++) {
                ldm4(Bh[g], bH + SWZ(oB[g] + ko));
                ldm4(Bl[g], bL + SWZ(oB[g] + ko));
            }
#pragma unroll
            for (int tm = 0; tm < 2; tm++)
#pragma unroll
                for (int tn = 0; tn < 4; tn++)
                    mma16816(Cr[tm][tn], Ah[tm],
                             Bh[tn >> 1][(tn & 1) * 2], Bh[tn >> 1][(tn & 1) * 2 + 1]);
#pragma unroll
            for (int tm = 0; tm < 2; tm++)
#pragma unroll
                for (int tn = 0; tn < 4; tn++)
                    mma16816(Cr[tm][tn], Al[tm],
                             Bh[tn >> 1][(tn & 1) * 2], Bh[tn >> 1][(tn & 1) * 2 + 1]);
#pragma unroll
            for (int tm = 0; tm < 2; tm++)
#pragma unroll
                for (int tn = 0; tn < 4; tn++)
                    mma16816(Cr[tm][tn], Ah[tm],
                             Bl[tn >> 1][(tn & 1) * 2], Bl[tn >> 1][(tn & 1) * 2 + 1]);
        }
        __syncthreads();
    }

    // ------------------------------ epilogue --------------------------------
    const int r0 = blockM + wm * 32 + (lane >> 2);
    const int n0 = blockN + wn * 32 + 2 * (lane & 3);
#pragma unroll
    for (int tm = 0; tm < 2; tm++) {
#pragma unroll
        for (int tn = 0; tn < 4; tn++) {
            int n = n0 + tn * 8;
            float bx = bias[n], by = bias[n + 1];
#pragma unroll
            for (int half = 0; half < 2; half++) {
                int m = r0 + tm * 16 + half * 8;
                float vx = Cr[tm][tn][half * 2 + 0] + bx;
                float vy = Cr[tm][tn][half * 2 + 1] + by;
                if (MODE == 0) {
                    *(float2*)(g_qkv + (size_t)m * 576 + n) = make_float2(vx, vy);
                } else if (MODE == 1) {
                    size_t idx = (size_t)g_rowmap[m] * CC + n;
                    float2 a = *(const float2*)(aux + idx);
                    *(float2*)(g_xnew + idx) = make_float2(vx + a.x, vy + a.y);
                } else if (MODE == 2) {
                    vx = 0.5f * vx * (1.f + erff(vx * 0.70710678118654752f));
                    vy = 0.5f * vy * (1.f + erff(vy * 0.70710678118654752f));
                    __nv_bfloat162 h = __floats2bfloat162_rn(vx, vy);
                    __nv_bfloat162 l = __floats2bfloat162_rn(
                        vx - __bfloat162float(h.x), vy - __bfloat162float(h.y));
                    __nv_bfloat16* row = g_hid + (size_t)m * 1536;
                    *(uint32_t*)(row + n)       = b2u(h);
                    *(uint32_t*)(row + 768 + n) = b2u(l);
                } else {
                    size_t idx = (size_t)m * CC + n;
                    float2 a = *(const float2*)(g_xnew + idx);
                    *(float2*)(outp + idx) = make_float2(vx + a.x, vy + a.y);
                }
            }
        }
    }
}

// ------------------------------ attention -----------------------------------
// float4-vectorized (stride-36 rows); writes split-bf16 g_attn.
__global__ __launch_bounds__(256)
void attn_kernel(const float* __restrict__ rpb) {
    __shared__ __align__(16) float sq[52 * 36];
    __shared__ __align__(16) float sk[52 * 36];
    __shared__ __align__(16) float sv[52 * 36];
    __shared__ float sS[NTOK * 50];
    __shared__ float srpb[169];
    __shared__ int   slabel[NTOK];

    const int bwin = blockIdx.x;
    const int head = blockIdx.y;
    const int tid  = threadIdx.x;
    const float scale = 0.17677669529663687f;

    const size_t rbase = (size_t)(bwin * NTOK) * 576 + head * HD_;
    for (int idx = tid; idx < NTOK * HD_; idx += 256) {
        int tok = idx >> 5, d = idx & 31;
        const float* r = g_qkv + rbase + (size_t)tok * 576;
        sq[tok * 36 + d] = r[d] * scale;
        sk[tok * 36 + d] = r[192 + d];
        sv[tok * 36 + d] = r[384 + d];
    }
    for (int t = tid; t < 169; t += 256) srpb[t] = rpb[t * NH_ + head];
    if (tid < NTOK) {
        int w = bwin & 63;
        int wh = w >> 3, ww = w & 7;
        int r = tid / WS_, c = tid - r * WS_;
        int gh = wh * WS_ + r, gw = ww * WS_ + c;
        int rr = (gh < HH - WS_) ? 0 : (gh < HH - SS_) ? 1 : 2;
        int cc = (gw < WW_ - WS_) ? 0 : (gw < WW_ - SS_) ? 1 : 2;
        slabel[tid] = rr * 3 + cc;
    }
    // zero pad rows so vector loads of j0+1..3 >= 49 are harmless
    for (int t = tid; t < 3 * 36; t += 256) {
        sk[49 * 36 + t] = 0.f;
        sv[49 * 36 + t] = 0.f;
    }
    __syncthreads();

    // S = q k^T + bias + mask (4 j per thread, float4 over d)
    for (int e = tid; e < NTOK * 13; e += 256) {
        int i = e / 13, j0 = (e - i * 13) * 4;
        float4 s0 = make_float4(0, 0, 0, 0), s1 = s0, s2 = s0, s3 = s0;
        const float4* q4 = (const float4*)&sq[i * 36];
        const float* kb = &sk[j0 * 36];
#pragma unroll
        for (int d4 = 0; d4 < 8; d4++) {
            float4 q = q4[d4];
            float4 k0 = *(const float4*)(kb + d4 * 4);
            float4 k1 = *(const float4*)(kb + 36 + d4 * 4);
            float4 k2 = *(const float4*)(kb + 72 + d4 * 4);
            float4 k3 = *(const float4*)(kb + 108 + d4 * 4);
            s0.x += q.x * k0.x; s0.y += q.y * k0.y; s0.z += q.z * k0.z; s0.w += q.w * k0.w;
            s1.x += q.x * k1.x; s1.y += q.y * k1.y; s1.z += q.z * k1.z; s1.w += q.w * k1.w;
            s2.x += q.x * k2.x; s2.y += q.y * k2.y; s2.z += q.z * k2.z; s2.w += q.w * k2.w;
            s3.x += q.x * k3.x; s3.y += q.y * k3.y; s3.z += q.z * k3.z; s3.w += q.w * k3.w;
        }
        float acc[4] = { s0.x + s0.y + s0.z + s0.w, s1.x + s1.y + s1.z + s1.w,
                         s2.x + s2.y + s2.z + s2.w, s3.x + s3.y + s3.z + s3.w };
        int ri = i / WS_, ci = i - ri * WS_;
        int li = slabel[i];
#pragma unroll
        for (int t = 0; t < 4; t++) {
            int j = j0 + t;
            if (j < NTOK) {
                int rj = j / WS_, cj = j - rj * WS_;
                float a = acc[t] + srpb[(ri - rj + 6) * 13 + (ci - cj + 6)];
                if (li != slabel[j]) a -= 100.f;
                sS[i * 50 + j] = a;
            }
        }
    }
    __syncthreads();

    // softmax: warp per row
    {
        int warp = tid >> 5, lane = tid & 31;
        for (int i = warp; i < NTOK; i += 8) {
            float mx = -1e30f;
            for (int j = lane; j < NTOK; j += 32) mx = fmaxf(mx, sS[i * 50 + j]);
#pragma unroll
            for (int o = 16; o > 0; o >>= 1) mx = fmaxf(mx, __shfl_xor_sync(0xffffffffu, mx, o));
            float s = 0.f;
            for (int j = lane; j < NTOK; j += 32) {
                float e = __expf(sS[i * 50 + j] - mx);
                sS[i * 50 + j] = e;
                s += e;
            }
#pragma unroll
            for (int o = 16; o > 0; o >>= 1) s += __shfl_xor_sync(0xffffffffu, s, o);
            float inv = 1.f / s;
            for (int j = lane; j < NTOK; j += 32) sS[i * 50 + j] *= inv;
        }
    }
    __syncthreads();

    // O = P V (float4 over d), split-bf16 out
    for (int e = tid; e < NTOK * 8; e += 256) {
        int i = e >> 3, d0 = (e & 7) * 4;
        float4 acc = make_float4(0, 0, 0, 0);
        const float* Si = &sS[i * 50];
        const float* vb = &sv[d0];
#pragma unroll
        for (int j = 0; j < NTOK; j++) {
            float s_ = Si[j];
            float4 v = *(const float4*)(vb + j * 36);
            acc.x += s_ * v.x; acc.y += s_ * v.y;
            acc.z += s_ * v.z; acc.w += s_ * v.w;
        }
        __nv_bfloat162 h01 = __floats2bfloat162_rn(acc.x, acc.y);
        __nv_bfloat162 h23 = __floats2bfloat162_rn(acc.z, acc.w);
        __nv_bfloat162 l01 = __floats2bfloat162_rn(acc.x - __bfloat162float(h01.x),
                                                   acc.y - __bfloat162float(h01.y));
        __nv_bfloat162 l23 = __floats2bfloat162_rn(acc.z - __bfloat162float(h23.x),
                                                   acc.w - __bfloat162float(h23.y));
        __nv_bfloat16* row = g_attn + (size_t)(bwin * NTOK + i) * 384 + head * HD_ + d0;
        *(uint2*)row         = make_uint2(b2u(h01), b2u(h23));
        *(uint2*)(row + 192) = make_uint2(b2u(l01), b2u(l23));
    }
}

// ------------------------------- launch -------------------------------------
extern "C" void kernel_launch(void* const* d_in, const int* in_sizes, int n_in,
                              void* d_out, int out_size) {
    const float* x       = (const float*)d_in[0];
    const float* norm1_w = (const float*)d_in[1];
    const float* norm1_b = (const float*)d_in[2];
    const float* qkv_w   = (const float*)d_in[3];
    const float* qkv_b   = (const float*)d_in[4];
    const float* rpb     = (const float*)d_in[5];
    const float* proj_w  = (const float*)d_in[6];
    const float* proj_b  = (const float*)d_in[7];
    const float* norm2_w = (const float*)d_in[8];
    const float* norm2_b = (const float*)d_in[9];
    const float* fc1_w   = (const float*)d_in[10];
    const float* fc1_b   = (const float*)d_in[11];
    const float* fc2_w   = (const float*)d_in[12];
    const float* fc2_b   = (const float*)d_in[13];
    float* out = (float*)d_out;

    __nv_bfloat16 *p_ln, *p_attn, *p_hid, *p_wqkv, *p_wproj, *p_wfc1, *p_wfc2;
    float *p_xnew;
    cudaGetSymbolAddress((void**)&p_ln,    g_ln);
    cudaGetSymbolAddress((void**)&p_attn,  g_attn);
    cudaGetSymbolAddress((void**)&p_hid,   g_hid);
    cudaGetSymbolAddress((void**)&p_xnew,  g_xnew);
    cudaGetSymbolAddress((void**)&p_wqkv,  g_wqkv);
    cudaGetSymbolAddress((void**)&p_wproj, g_wproj);
    cudaGetSymbolAddress((void**)&p_wfc1,  g_wfc1);
    cudaGetSymbolAddress((void**)&p_wfc2,  g_wfc2);

    const int SMEM = 2 * STAGE_B;
    cudaFuncSetAttribute(mma_gemm<192,0>, cudaFuncAttributeMaxDynamicSharedMemorySize, SMEM);
    cudaFuncSetAttribute(mma_gemm<192,1>, cudaFuncAttributeMaxDynamicSharedMemorySize, SMEM);
    cudaFuncSetAttribute(mma_gemm<192,2>, cudaFuncAttributeMaxDynamicSharedMemorySize, SMEM);
    cudaFuncSetAttribute(mma_gemm<768,3>, cudaFuncAttributeMaxDynamicSharedMemorySize, SMEM);

    rowmap_kernel<<<(MROWS + 255) / 256, 256>>>();
    wsplit_kernel<<<(192 * 576 + 255) / 256, 256>>>(qkv_w,  p_wqkv, 192, 576);
    wsplit_kernel<<<(192 * 192 + 255) / 256, 256>>>(proj_w, p_wproj, 192, 192);
    wsplit_kernel<<<(192 * 768 + 255) / 256, 256>>>(fc1_w,  p_wfc1, 192, 768);
    wsplit_kernel<<<(768 * 192 + 255) / 256, 256>>>(fc2_w,  p_wfc2, 768, 192);

    ln_kernel<<<MROWS / 8, 256>>>(x, norm1_w, norm1_b, p_ln);

    mma_gemm<192, 0><<<dim3(9, 1568), 256, SMEM>>>(p_ln, p_wqkv, qkv_b, nullptr, nullptr);

    attn_kernel<<<dim3(NWIN, NH_), 256>>>(rpb);

    mma_gemm<192, 1><<<dim3(3, 1568), 256, SMEM>>>(p_attn, p_wproj, proj_b, x, nullptr);

    ln_kernel<<<MROWS / 8, 256>>>(p_xnew, norm2_w, norm2_b, p_ln);

    mma_gemm<192, 2><<<dim3(12, 1568), 256, SMEM>>>(p_ln, p_wfc1, fc1_b, nullptr, nullptr);

    mma_gemm<768, 3><<<dim3(3, 1568), 256, SMEM>>>(p_hid, p_wfc2, fc2_b, nullptr, out);
}

// round 6
// speedup vs baseline: 1.4096x; 1.0701x over previous
#include <cuda_runtime.h>
#include <cuda_fp16.h>
#include <math.h>
#include <stdint.h>

// ---------------------------------------------------------------------------
// Swin block: 2-term split-fp16 HMMA GEMMs (hiA*hiB + loA*hiB), cp.async
// pipelines, presplit activations, fused epilogues, vectorized attention.
// ---------------------------------------------------------------------------

#define BATCH   64
#define HH      56
#define WW_     56
#define CC      192
#define WS_     7
#define SS_     3
#define NH_     6
#define HD_     32
#define NTOK    49
#define NWIN    4096
#define MROWS   200704
#define HIDDEN  768
#define EPS_    1e-5f

// ------------------------------- scratch -----------------------------------
// split-fp16 activation rows: [hi(K) | lo(K)]
__device__ __half g_ln  [(size_t)MROWS * 384];    // LN out (K=192)
__device__ __half g_attn[(size_t)MROWS * 384];    // attn out (K=192)
__device__ __half g_hid [(size_t)MROWS * 1536];   // GELU out (K=768)
__device__ float g_qkv [(size_t)MROWS * 576];     // window-order fp32
__device__ float g_xnew[(size_t)MROWS * CC];      // natural fp32
__device__ int   g_rowmap[MROWS];
// weights: [N][K] fp16 (hi only)
__device__ __half g_wqkv [576 * 192];
__device__ __half g_wproj[192 * 192];
__device__ __half g_wfc1 [768 * 192];
__device__ __half g_wfc2 [192 * 768];

// ------------------------------ helpers -------------------------------------
__device__ __forceinline__ uint32_t smem_u32(const void* p) {
    uint32_t a;
    asm("{ .reg .u64 t; cvta.to.shared.u64 t, %1; cvt.u32.u64 %0, t; }"
        : "=r"(a) : "l"(p));
    return a;
}
#define SWZ(o) ((o) ^ (((o) >> 3) & 0x70))

__device__ __forceinline__ void cp16(uint32_t dst, const void* src) {
    asm volatile("cp.async.cg.shared.global [%0], [%1], 16;"
                 :: "r"(dst), "l"(src));
}
__device__ __forceinline__ void cp_commit() {
    asm volatile("cp.async.commit_group;" ::: "memory");
}
__device__ __forceinline__ void cp_wait0() {
    asm volatile("cp.async.wait_group 0;" ::: "memory");
}
__device__ __forceinline__ void ldm4(uint32_t* r, uint32_t addr) {
    asm volatile("ldmatrix.sync.aligned.m8n8.x4.shared.b16 {%0,%1,%2,%3}, [%4];"
                 : "=r"(r[0]), "=r"(r[1]), "=r"(r[2]), "=r"(r[3]) : "r"(addr));
}
__device__ __forceinline__ void mma16816(float* c, const uint32_t* a,
                                         uint32_t b0, uint32_t b1) {
    asm volatile(
        "mma.sync.aligned.m16n8k16.row.col.f32.f16.f16.f32 "
        "{%0,%1,%2,%3}, {%4,%5,%6,%7}, {%8,%9}, {%0,%1,%2,%3};"
        : "+f"(c[0]), "+f"(c[1]), "+f"(c[2]), "+f"(c[3])
        : "r"(a[0]), "r"(a[1]), "r"(a[2]), "r"(a[3]), "r"(b0), "r"(b1));
}
__device__ __forceinline__ uint32_t h2u(__half2 v) { return *(uint32_t*)&v; }

// -------------------------- small prep kernels ------------------------------
__global__ void rowmap_kernel() {
    int m = blockIdx.x * 256 + threadIdx.x;
    if (m >= MROWS) return;
    int bwin = m / NTOK, tok = m - bwin * NTOK;
    int b  = bwin >> 6, w = bwin & 63;
    int wh = w >> 3, ww = w & 7;
    int r = tok / WS_, c = tok - r * WS_;
    int gh = wh * WS_ + r, gw = ww * WS_ + c;
    int oh = gh + SS_; if (oh >= HH)  oh -= HH;
    int ow = gw + SS_; if (ow >= WW_) ow -= WW_;
    g_rowmap[m] = (b * (HH * WW_) + oh * WW_ + ow);
}

// transpose fp32 [K,N] weights -> fp16 [N,K]
__global__ void whalf_kernel(const float* __restrict__ W,
                             __half* __restrict__ out, int Kd, int Nd) {
    int idx = blockIdx.x * 256 + threadIdx.x;
    if (idx >= Kd * Nd) return;
    int k = idx / Nd, n = idx - k * Nd;
    out[(size_t)n * Kd + k] = __float2half(W[idx]);
}

// LN: fp32 in -> split fp16 out ([hi192 | lo192] rows)
__global__ void ln_kernel(const float* __restrict__ in,
                          const float* __restrict__ w,
                          const float* __restrict__ b,
                          __half* __restrict__ out) {
    int row  = blockIdx.x * 8 + (threadIdx.x >> 5);
    int lane = threadIdx.x & 31;
    const float* p = in + (size_t)row * CC;
    float v[6];
    float s = 0.f;
#pragma unroll
    for (int i = 0; i < 6; i++) { v[i] = p[lane + 32 * i]; s += v[i]; }
#pragma unroll
    for (int o = 16; o > 0; o >>= 1) s += __shfl_xor_sync(0xffffffffu, s, o);
    float mean = s * (1.f / CC);
    float q = 0.f;
#pragma unroll
    for (int i = 0; i < 6; i++) { float d = v[i] - mean; q += d * d; }
#pragma unroll
    for (int o = 16; o > 0; o >>= 1) q += __shfl_xor_sync(0xffffffffu, q, o);
    float inv = rsqrtf(q * (1.f / CC) + EPS_);
    __half* op = out + (size_t)row * 384;
#pragma unroll
    for (int i = 0; i < 6; i++) {
        int c = lane + 32 * i;
        float y = (v[i] - mean) * inv * w[c] + b[c];
        __half h = __float2half(y);
        op[c]       = h;
        op[192 + c] = __float2half(y - __half2float(h));
    }
}

// ----------------------------- mma GEMM --------------------------------------
// C[128,64] tile = Asp[128,2K] x Bhi[N,K]^T, 2 terms: hiA*hiB + loA*hiB.
// BK = 64 fp32-k per chunk; cp.async double-buffered.
// stage: A-hi 16K | A-lo 16K | B-hi 8K (128B swizzled rows) = 40KB
#define STAGE_B 40960
template<int K, int MODE>
__global__ __launch_bounds__(256, 2)
void mma_gemm(const __half* __restrict__ A,
              const __half* __restrict__ Bhi,
              const float* __restrict__ bias,
              const float* __restrict__ aux,
              float* __restrict__ outp)
{
    extern __shared__ __align__(128) char dynsm[];
    constexpr int NCH = K / 64;
    constexpr int ARS = 2 * K;

    const int tid  = threadIdx.x;
    const int lane = tid & 31;
    const int warp = tid >> 5;
    const int wm = warp & 3;
    const int wn = warp >> 2;
    const int blockN = blockIdx.x * 64;
    const int blockM = blockIdx.y * 128;
    const uint32_t sb0 = smem_u32(dynsm);

    // per-thread cp.async descriptors
    const __half* aSrc[4];
    uint32_t aDst[4];
#pragma unroll
    for (int i = 0; i < 4; i++) {
        int idx = i * 256 + tid;
        int row = idx >> 3, u = idx & 7;
        int garow = (MODE == 0) ? g_rowmap[blockM + row] : (blockM + row);
        aSrc[i] = A + (size_t)garow * ARS + u * 8;
        aDst[i] = SWZ((uint32_t)(row * 128 + u * 16));
    }
    const __half* bSrc[2];
    uint32_t bDst[2];
#pragma unroll
    for (int i = 0; i < 2; i++) {
        int idx = i * 256 + tid;
        int n = idx >> 3, u = idx & 7;
        bSrc[i] = Bhi + (size_t)(blockN + n) * K + u * 8;
        bDst[i] = SWZ((uint32_t)(n * 128 + u * 16));
    }

    auto issue = [&](int c, int st) {
        const uint32_t sb = sb0 + st * STAGE_B;
#pragma unroll
        for (int i = 0; i < 4; i++) {
            cp16(sb + aDst[i],         aSrc[i] + c * 64);       // A hi
            cp16(sb + 16384 + aDst[i], aSrc[i] + K + c * 64);   // A lo
        }
#pragma unroll
        for (int i = 0; i < 2; i++)
            cp16(sb + 32768 + bDst[i], bSrc[i] + c * 64);       // B hi
    };

    // fragment offsets
    uint32_t oA[2], oB[2];
#pragma unroll
    for (int tm = 0; tm < 2; tm++)
        oA[tm] = (uint32_t)((wm * 32 + tm * 16 + (lane & 15)) * 128 + (lane >> 4) * 16);
#pragma unroll
    for (int g = 0; g < 2; g++)
        oB[g] = (uint32_t)((wn * 32 + g * 16 + (lane & 7) + ((lane >> 4) & 1) * 8) * 128
                           + ((lane >> 3) & 1) * 16);

    float Cr[2][4][4];
#pragma unroll
    for (int a = 0; a < 2; a++)
#pragma unroll
        for (int b = 0; b < 4; b++)
#pragma unroll
            for (int c = 0; c < 4; c++) Cr[a][b][c] = 0.f;

    issue(0, 0);
    cp_commit();

    for (int c = 0; c < NCH; c++) {
        const int st = c & 1;
        cp_wait0();
        __syncthreads();
        if (c + 1 < NCH) { issue(c + 1, st ^ 1); cp_commit(); }

        const uint32_t aH = sb0 + st * STAGE_B;
        const uint32_t aL = aH + 16384;
        const uint32_t bH = aH + 32768;
#pragma unroll
        for (int k16 = 0; k16 < 4; k16++) {
            const uint32_t ko = k16 * 32;
            uint32_t Ah[2][4], Al[2][4], Bh[2][4];
#pragma unroll
            for (int tm = 0; tm < 2; tm++) {
                ldm4(Ah[tm], aH + SWZ(oA[tm] + ko));
                ldm4(Al[tm], aL + SWZ(oA[tm] + ko));
            }
#pragma unroll
            for (int g = 0; g < 2; g++)
                ldm4(Bh[g], bH + SWZ(oB[g] + ko));
#pragma unroll
            for (int tm = 0; tm < 2; tm++)
#pragma unroll
                for (int tn = 0; tn < 4; tn++)
                    mma16816(Cr[tm][tn], Ah[tm],
                             Bh[tn >> 1][(tn & 1) * 2], Bh[tn >> 1][(tn & 1) * 2 + 1]);
#pragma unroll
            for (int tm = 0; tm < 2; tm++)
#pragma unroll
                for (int tn = 0; tn < 4; tn++)
                    mma16816(Cr[tm][tn], Al[tm],
                             Bh[tn >> 1][(tn & 1) * 2], Bh[tn >> 1][(tn & 1) * 2 + 1]);
        }
        __syncthreads();
    }

    // ------------------------------ epilogue --------------------------------
    const int r0 = blockM + wm * 32 + (lane >> 2);
    const int n0 = blockN + wn * 32 + 2 * (lane & 3);
#pragma unroll
    for (int tm = 0; tm < 2; tm++) {
#pragma unroll
        for (int tn = 0; tn < 4; tn++) {
            int n = n0 + tn * 8;
            float bx = bias[n], by = bias[n + 1];
#pragma unroll
            for (int half_ = 0; half_ < 2; half_++) {
                int m = r0 + tm * 16 + half_ * 8;
                float vx = Cr[tm][tn][half_ * 2 + 0] + bx;
                float vy = Cr[tm][tn][half_ * 2 + 1] + by;
                if (MODE == 0) {
                    *(float2*)(g_qkv + (size_t)m * 576 + n) = make_float2(vx, vy);
                } else if (MODE == 1) {
                    size_t idx = (size_t)g_rowmap[m] * CC + n;
                    float2 a = *(const float2*)(aux + idx);
                    *(float2*)(g_xnew + idx) = make_float2(vx + a.x, vy + a.y);
                } else if (MODE == 2) {
                    vx = 0.5f * vx * (1.f + erff(vx * 0.70710678118654752f));
                    vy = 0.5f * vy * (1.f + erff(vy * 0.70710678118654752f));
                    __half2 h = __floats2half2_rn(vx, vy);
                    __half2 l = __floats2half2_rn(vx - __half2float(__low2half(h)),
                                                  vy - __half2float(__high2half(h)));
                    __half* row = g_hid + (size_t)m * 1536;
                    *(uint32_t*)(row + n)       = h2u(h);
                    *(uint32_t*)(row + 768 + n) = h2u(l);
                } else {
                    size_t idx = (size_t)m * CC + n;
                    float2 a = *(const float2*)(g_xnew + idx);
                    *(float2*)(outp + idx) = make_float2(vx + a.x, vy + a.y);
                }
            }
        }
    }
}

// ------------------------------ attention -----------------------------------
// float4-vectorized (stride-36 rows); writes split-fp16 g_attn.
__global__ __launch_bounds__(256)
void attn_kernel(const float* __restrict__ rpb) {
    __shared__ __align__(16) float sq[52 * 36];
    __shared__ __align__(16) float sk[52 * 36];
    __shared__ __align__(16) float sv[52 * 36];
    __shared__ float sS[NTOK * 50];
    __shared__ float srpb[169];
    __shared__ int   slabel[NTOK];

    const int bwin = blockIdx.x;
    const int head = blockIdx.y;
    const int tid  = threadIdx.x;
    const float scale = 0.17677669529663687f;

    const size_t rbase = (size_t)(bwin * NTOK) * 576 + head * HD_;
    for (int idx = tid; idx < NTOK * HD_; idx += 256) {
        int tok = idx >> 5, d = idx & 31;
        const float* r = g_qkv + rbase + (size_t)tok * 576;
        sq[tok * 36 + d] = r[d] * scale;
        sk[tok * 36 + d] = r[192 + d];
        sv[tok * 36 + d] = r[384 + d];
    }
    for (int t = tid; t < 169; t += 256) srpb[t] = rpb[t * NH_ + head];
    if (tid < NTOK) {
        int w = bwin & 63;
        int wh = w >> 3, ww = w & 7;
        int r = tid / WS_, c = tid - r * WS_;
        int gh = wh * WS_ + r, gw = ww * WS_ + c;
        int rr = (gh < HH - WS_) ? 0 : (gh < HH - SS_) ? 1 : 2;
        int cc = (gw < WW_ - WS_) ? 0 : (gw < WW_ - SS_) ? 1 : 2;
        slabel[tid] = rr * 3 + cc;
    }
    for (int t = tid; t < 3 * 36; t += 256) {
        sk[49 * 36 + t] = 0.f;
        sv[49 * 36 + t] = 0.f;
    }
    __syncthreads();

    // S = q k^T + bias + mask (4 j per thread, float4 over d)
    for (int e = tid; e < NTOK * 13; e += 256) {
        int i = e / 13, j0 = (e - i * 13) * 4;
        float4 s0 = make_float4(0, 0, 0, 0), s1 = s0, s2 = s0, s3 = s0;
        const float4* q4 = (const float4*)&sq[i * 36];
        const float* kb = &sk[j0 * 36];
#pragma unroll
        for (int d4 = 0; d4 < 8; d4++) {
            float4 q = q4[d4];
            float4 k0 = *(const float4*)(kb + d4 * 4);
            float4 k1 = *(const float4*)(kb + 36 + d4 * 4);
            float4 k2 = *(const float4*)(kb + 72 + d4 * 4);
            float4 k3 = *(const float4*)(kb + 108 + d4 * 4);
            s0.x += q.x * k0.x; s0.y += q.y * k0.y; s0.z += q.z * k0.z; s0.w += q.w * k0.w;
            s1.x += q.x * k1.x; s1.y += q.y * k1.y; s1.z += q.z * k1.z; s1.w += q.w * k1.w;
            s2.x += q.x * k2.x; s2.y += q.y * k2.y; s2.z += q.z * k2.z; s2.w += q.w * k2.w;
            s3.x += q.x * k3.x; s3.y += q.y * k3.y; s3.z += q.z * k3.z; s3.w += q.w * k3.w;
        }
        float acc[4] = { s0.x + s0.y + s0.z + s0.w, s1.x + s1.y + s1.z + s1.w,
                         s2.x + s2.y + s2.z + s2.w, s3.x + s3.y + s3.z + s3.w };
        int ri = i / WS_, ci = i - ri * WS_;
        int li = slabel[i];
#pragma unroll
        for (int t = 0; t < 4; t++) {
            int j = j0 + t;
            if (j < NTOK) {
                int rj = j / WS_, cj = j - rj * WS_;
                float a = acc[t] + srpb[(ri - rj + 6) * 13 + (ci - cj + 6)];
                if (li != slabel[j]) a -= 100.f;
                sS[i * 50 + j] = a;
            }
        }
    }
    __syncthreads();

    // softmax: warp per row
    {
        int warp = tid >> 5, lane = tid & 31;
        for (int i = warp; i < NTOK; i += 8) {
            float mx = -1e30f;
            for (int j = lane; j < NTOK; j += 32) mx = fmaxf(mx, sS[i * 50 + j]);
#pragma unroll
            for (int o = 16; o > 0; o >>= 1) mx = fmaxf(mx, __shfl_xor_sync(0xffffffffu, mx, o));
            float s = 0.f;
            for (int j = lane; j < NTOK; j += 32) {
                float e = __expf(sS[i * 50 + j] - mx);
                sS[i * 50 + j] = e;
                s += e;
            }
#pragma unroll
            for (int o = 16; o > 0; o >>= 1) s += __shfl_xor_sync(0xffffffffu, s, o);
            float inv = 1.f / s;
            for (int j = lane; j < NTOK; j += 32) sS[i * 50 + j] *= inv;
        }
    }
    __syncthreads();

    // O = P V (float4 over d), split-fp16 out
    for (int e = tid; e < NTOK * 8; e += 256) {
        int i = e >> 3, d0 = (e & 7) * 4;
        float4 acc = make_float4(0, 0, 0, 0);
        const float* Si = &sS[i * 50];
        const float* vb = &sv[d0];
#pragma unroll
        for (int j = 0; j < NTOK; j++) {
            float s_ = Si[j];
            float4 v = *(const float4*)(vb + j * 36);
            acc.x += s_ * v.x; acc.y += s_ * v.y;
            acc.z += s_ * v.z; acc.w += s_ * v.w;
        }
        __half2 h01 = __floats2half2_rn(acc.x, acc.y);
        __half2 h23 = __floats2half2_rn(acc.z, acc.w);
        __half2 l01 = __floats2half2_rn(acc.x - __half2float(__low2half(h01)),
                                        acc.y - __half2float(__high2half(h01)));
        __half2 l23 = __floats2half2_rn(acc.z - __half2float(__low2half(h23)),
                                        acc.w - __half2float(__high2half(h23)));
        __half* row = g_attn + (size_t)(bwin * NTOK + i) * 384 + head * HD_ + d0;
        *(uint2*)row         = make_uint2(h2u(h01), h2u(h23));
        *(uint2*)(row + 192) = make_uint2(h2u(l01), h2u(l23));
    }
}

// ------------------------------- launch -------------------------------------
extern "C" void kernel_launch(void* const* d_in, const int* in_sizes, int n_in,
                              void* d_out, int out_size) {
    const float* x       = (const float*)d_in[0];
    const float* norm1_w = (const float*)d_in[1];
    const float* norm1_b = (const float*)d_in[2];
    const float* qkv_w   = (const float*)d_in[3];
    const float* qkv_b   = (const float*)d_in[4];
    const float* rpb     = (const float*)d_in[5];
    const float* proj_w  = (const float*)d_in[6];
    const float* proj_b  = (const float*)d_in[7];
    const float* norm2_w = (const float*)d_in[8];
    const float* norm2_b = (const float*)d_in[9];
    const float* fc1_w   = (const float*)d_in[10];
    const float* fc1_b   = (const float*)d_in[11];
    const float* fc2_w   = (const float*)d_in[12];
    const float* fc2_b   = (const float*)d_in[13];
    float* out = (float*)d_out;

    __half *p_ln, *p_attn, *p_hid, *p_wqkv, *p_wproj, *p_wfc1, *p_wfc2;
    float *p_xnew;
    cudaGetSymbolAddress((void**)&p_ln,    g_ln);
    cudaGetSymbolAddress((void**)&p_attn,  g_attn);
    cudaGetSymbolAddress((void**)&p_hid,   g_hid);
    cudaGetSymbolAddress((void**)&p_xnew,  g_xnew);
    cudaGetSymbolAddress((void**)&p_wqkv,  g_wqkv);
    cudaGetSymbolAddress((void**)&p_wproj, g_wproj);
    cudaGetSymbolAddress((void**)&p_wfc1,  g_wfc1);
    cudaGetSymbolAddress((void**)&p_wfc2,  g_wfc2);

    const int SMEM = 2 * STAGE_B;
    cudaFuncSetAttribute(mma_gemm<192,0>, cudaFuncAttributeMaxDynamicSharedMemorySize, SMEM);
    cudaFuncSetAttribute(mma_gemm<192,1>, cudaFuncAttributeMaxDynamicSharedMemorySize, SMEM);
    cudaFuncSetAttribute(mma_gemm<192,2>, cudaFuncAttributeMaxDynamicSharedMemorySize, SMEM);
    cudaFuncSetAttribute(mma_gemm<768,3>, cudaFuncAttributeMaxDynamicSharedMemorySize, SMEM);

    rowmap_kernel<<<(MROWS + 255) / 256, 256>>>();
    whalf_kernel<<<(192 * 576 + 255) / 256, 256>>>(qkv_w,  p_wqkv, 192, 576);
    whalf_kernel<<<(192 * 192 + 255) / 256, 256>>>(proj_w, p_wproj, 192, 192);
    whalf_kernel<<<(192 * 768 + 255) / 256, 256>>>(fc1_w,  p_wfc1, 192, 768);
    whalf_kernel<<<(768 * 192 + 255) / 256, 256>>>(fc2_w,  p_wfc2, 768, 192);

    ln_kernel<<<MROWS / 8, 256>>>(x, norm1_w, norm1_b, p_ln);

    mma_gemm<192, 0><<<dim3(9, 1568), 256, SMEM>>>(p_ln, p_wqkv, qkv_b, nullptr, nullptr);

    attn_kernel<<<dim3(NWIN, NH_), 256>>>(rpb);

    mma_gemm<192, 1><<<dim3(3, 1568), 256, SMEM>>>(p_attn, p_wproj, proj_b, x, nullptr);

    ln_kernel<<<MROWS / 8, 256>>>(p_xnew, norm2_w, norm2_b, p_ln);

    mma_gemm<192, 2><<<dim3(12, 1568), 256, SMEM>>>(p_ln, p_wfc1, fc1_b, nullptr, nullptr);

    mma_gemm<768, 3><<<dim3(3, 1568), 256, SMEM>>>(p_hid, p_wfc2, fc2_b, nullptr, out);
}